// round 1
// baseline (speedup 1.0000x reference)
#include <cuda_runtime.h>
#include <math.h>

#define HIDDEN 256
#define INPUT  13
#define SEQ    5
#define OUTD   6
#define GATES  1024          // 4*HIDDEN
#define BM     64            // batch rows per block
#define NTHREADS 256

// Static device scratch (allocation-free rule): transposed weights.
__device__ float g_Wt[HIDDEN * GATES];    // [k][gaterow]  (W_hh transposed)
__device__ float g_WihT[INPUT * GATES];   // [k][gaterow]  (W_ih transposed)

__global__ void prep_kernel(const float* __restrict__ W_ih,
                            const float* __restrict__ W_hh) {
    int idx = blockIdx.x * blockDim.x + threadIdx.x;
    if (idx < HIDDEN * GATES) {
        int k = idx / GATES, r = idx % GATES;
        g_Wt[idx] = W_hh[r * HIDDEN + k];
    }
    if (idx < INPUT * GATES) {
        int k = idx / GATES, r = idx % GATES;
        g_WihT[idx] = W_ih[r * INPUT + k];
    }
}

__device__ __forceinline__ float fast_sigmoid(float x) {
    return 1.0f / (1.0f + __expf(-x));
}
__device__ __forceinline__ float fast_tanh(float x) {
    return 2.0f / (1.0f + __expf(-2.0f * x)) - 1.0f;
}

// Shared memory partition sizes (floats)
#define HS_FLOATS   (2 * HIDDEN * BM)      // 32768
#define WS_FLOATS   (16 * 256)             // 4096
#define WIH_FLOATS  (INPUT * GATES)        // 13312
#define XS_FLOATS   (SEQ * INPUT * BM)     // 4160
#define BIAS_FLOATS (GATES)                // 1024
#define OUT_FLOATS  (OUTD * BM)            // 384
#define SMEM_FLOATS (HS_FLOATS + WS_FLOATS + WIH_FLOATS + XS_FLOATS + BIAS_FLOATS + OUT_FLOATS)
#define SMEM_BYTES  (SMEM_FLOATS * 4)      // 222976 bytes

__global__ __launch_bounds__(NTHREADS, 1)
void lstm_kernel(const float* __restrict__ x,      // [B, 5, 13]
                 const float* __restrict__ b_ih,   // [1024]
                 const float* __restrict__ b_hh,   // [1024]
                 const float* __restrict__ W1,     // [6, 1280]
                 const float* __restrict__ b1,     // [6]
                 float* __restrict__ out) {        // [B, 6]
    extern __shared__ float smem[];
    float* Hs    = smem;                          // [2][256][64] k-major
    float* Ws    = Hs + HS_FLOATS;                // [16][256]
    float* WihS  = Ws + WS_FLOATS;                // [13][1024]
    float* Xs    = WihS + WIH_FLOATS;             // [5][13][64]
    float* biasS = Xs + XS_FLOATS;                // [1024]
    float* outS  = biasS + BIAS_FLOATS;           // [6][64]  (oc*64+row)

    const int tid = threadIdx.x;
    const int tx  = tid & 15;        // 16 column-groups
    const int ty  = tid >> 4;        // 16 row-groups (4 rows each)
    const int row0 = blockIdx.x * BM;

    // ---- stage per-block constants ----
    for (int i = tid; i < WIH_FLOATS; i += NTHREADS) WihS[i] = g_WihT[i];
    for (int i = tid; i < GATES; i += NTHREADS)      biasS[i] = b_ih[i] + b_hh[i];
    // input tile, transposed to [t][k][row]
    for (int i = tid; i < BM * SEQ * INPUT; i += NTHREADS) {
        int row = i / (SEQ * INPUT);
        int j   = i % (SEQ * INPUT);
        Xs[j * BM + row] = x[(size_t)(row0 + row) * (SEQ * INPUT) + j];
    }
    for (int i = tid; i < OUTD * BM; i += NTHREADS) outS[i] = b1[i >> 6];
    __syncthreads();

    // cell state: [chunk][r][j] -> 64 registers
    float c_reg[64];
    #pragma unroll
    for (int i = 0; i < 64; i++) c_reg[i] = 0.0f;

    for (int t = 0; t < SEQ; t++) {
        const int cur = t & 1, nxt = cur ^ 1;
        float* Hcur = Hs + cur * HIDDEN * BM;
        float* Hnxt = Hs + nxt * HIDDEN * BM;

        #pragma unroll
        for (int chunk = 0; chunk < 4; chunk++) {
            const int colb = chunk * 64 + tx * 4;   // h-col base for this thread
            float acc[64];                          // [r][g*4+j]

            // init with gate bias (same for all 4 rows)
            #pragma unroll
            for (int g = 0; g < 4; g++) {
                float4 bv = *(const float4*)&biasS[g * HIDDEN + colb];
                #pragma unroll
                for (int r = 0; r < 4; r++) {
                    acc[r * 16 + g * 4 + 0] = bv.x;
                    acc[r * 16 + g * 4 + 1] = bv.y;
                    acc[r * 16 + g * 4 + 2] = bv.z;
                    acc[r * 16 + g * 4 + 3] = bv.w;
                }
            }

            // input projection: K = 13
            #pragma unroll
            for (int k = 0; k < INPUT; k++) {
                float4 a = *(const float4*)&Xs[(t * INPUT + k) * BM + ty * 4];
                float av[4] = {a.x, a.y, a.z, a.w};
                #pragma unroll
                for (int g = 0; g < 4; g++) {
                    float4 b = *(const float4*)&WihS[k * GATES + g * HIDDEN + colb];
                    float bv[4] = {b.x, b.y, b.z, b.w};
                    #pragma unroll
                    for (int r = 0; r < 4; r++)
                        #pragma unroll
                        for (int j = 0; j < 4; j++)
                            acc[r * 16 + g * 4 + j] += av[r] * bv[j];
                }
            }

            // recurrent GEMM: K = 256 (skip at t=0 since h0 = 0)
            if (t > 0) {
                for (int k0 = 0; k0 < HIDDEN; k0 += 16) {
                    __syncthreads();   // protect Ws reuse
                    {
                        const int kk = tid >> 4, c = tid & 15;
                        const float* src = g_Wt + (size_t)(k0 + kk) * GATES;
                        #pragma unroll
                        for (int q = 0; q < 4; q++) {
                            int n  = c * 16 + q * 4;
                            int gr = (n >> 6) * HIDDEN + chunk * 64 + (n & 63);
                            *(float4*)&Ws[kk * 256 + n] = *(const float4*)&src[gr];
                        }
                    }
                    __syncthreads();
                    #pragma unroll 4
                    for (int kk = 0; kk < 16; kk++) {
                        float4 a = *(const float4*)&Hcur[(k0 + kk) * BM + ty * 4];
                        float av[4] = {a.x, a.y, a.z, a.w};
                        #pragma unroll
                        for (int g = 0; g < 4; g++) {
                            float4 b = *(const float4*)&Ws[kk * 256 + g * 64 + tx * 4];
                            float bv[4] = {b.x, b.y, b.z, b.w};
                            #pragma unroll
                            for (int r = 0; r < 4; r++)
                                #pragma unroll
                                for (int j = 0; j < 4; j++)
                                    acc[r * 16 + g * 4 + j] += av[r] * bv[j];
                        }
                    }
                }
            }

            // fused LSTM pointwise; write h to next buffer (k-major)
            #pragma unroll
            for (int j = 0; j < 4; j++) {
                float hv[4];
                #pragma unroll
                for (int r = 0; r < 4; r++) {
                    float ig = fast_sigmoid(acc[r * 16 + 0  + j]);
                    float fg = fast_sigmoid(acc[r * 16 + 4  + j]);
                    float gg = fast_tanh   (acc[r * 16 + 8  + j]);
                    float og = fast_sigmoid(acc[r * 16 + 12 + j]);
                    int ci = chunk * 16 + r * 4 + j;
                    float cn = fg * c_reg[ci] + ig * gg;
                    c_reg[ci] = cn;
                    hv[r] = og * fast_tanh(cn);
                }
                *(float4*)&Hnxt[(colb + j) * BM + ty * 4] =
                    make_float4(hv[0], hv[1], hv[2], hv[3]);
            }
        }
        __syncthreads();   // all h(t) written before projection reads

        // accumulate output projection for this timestep
        for (int task = tid; task < OUTD * BM; task += NTHREADS) {
            int row = task & 63, oc = task >> 6;
            const float* w = W1 + (size_t)oc * (SEQ * HIDDEN) + t * HIDDEN;
            float sum = 0.0f;
            #pragma unroll 8
            for (int k = 0; k < HIDDEN; k++)
                sum += Hnxt[k * BM + row] * w[k];
            outS[task] += sum;
        }
        __syncthreads();
    }

    for (int task = tid; task < OUTD * BM; task += NTHREADS) {
        int row = task & 63, oc = task >> 6;
        out[(size_t)(row0 + row) * OUTD + oc] = outS[task];
    }
}

extern "C" void kernel_launch(void* const* d_in, const int* in_sizes, int n_in,
                              void* d_out, int out_size) {
    const float* x    = (const float*)d_in[0];
    const float* W_ih = (const float*)d_in[1];
    const float* W_hh = (const float*)d_in[2];
    const float* b_ih = (const float*)d_in[3];
    const float* b_hh = (const float*)d_in[4];
    const float* W1   = (const float*)d_in[5];
    const float* b1   = (const float*)d_in[6];
    float* out = (float*)d_out;

    int B = in_sizes[0] / (SEQ * INPUT);

    prep_kernel<<<(HIDDEN * GATES + 255) / 256, 256>>>(W_ih, W_hh);

    cudaFuncSetAttribute(lstm_kernel,
                         cudaFuncAttributeMaxDynamicSharedMemorySize, SMEM_BYTES);
    lstm_kernel<<<B / BM, NTHREADS, SMEM_BYTES>>>(x, b_ih, b_hh, W1, b1, out);
}

// round 2
// speedup vs baseline: 1.0005x; 1.0005x over previous
#include <cuda_runtime.h>
#include <math.h>

#define HIDDEN 256
#define INPUT  13
#define SEQ    5
#define OUTD   6
#define GATES  1024          // 4*HIDDEN
#define BM     64            // batch rows per block
#define NTHREADS 256

// Static device scratch (allocation-free rule): transposed weights.
__device__ float g_Wt[HIDDEN * GATES];    // [k][gaterow]  (W_hh transposed)
__device__ float g_WihT[INPUT * GATES];   // [k][gaterow]  (W_ih transposed)

__global__ void prep_kernel(const float* __restrict__ W_ih,
                            const float* __restrict__ W_hh) {
    int idx = blockIdx.x * blockDim.x + threadIdx.x;
    if (idx < HIDDEN * GATES) {
        int k = idx / GATES, r = idx % GATES;
        g_Wt[idx] = W_hh[r * HIDDEN + k];
    }
    if (idx < INPUT * GATES) {
        int k = idx / GATES, r = idx % GATES;
        g_WihT[idx] = W_ih[r * INPUT + k];
    }
}

__device__ __forceinline__ float fast_sigmoid(float x) {
    return 1.0f / (1.0f + __expf(-x));
}
__device__ __forceinline__ float fast_tanh(float x) {
    return 2.0f / (1.0f + __expf(-2.0f * x)) - 1.0f;
}

// Shared memory partition sizes (floats)
#define HS_FLOATS   (2 * HIDDEN * BM)      // 32768
#define WS_FLOATS   (16 * 256)             // 4096
#define WIH_FLOATS  (INPUT * GATES)        // 13312
#define XS_FLOATS   (SEQ * INPUT * BM)     // 4160
#define BIAS_FLOATS (GATES)                // 1024
#define OUT_FLOATS  (OUTD * BM)            // 384
#define SMEM_FLOATS (HS_FLOATS + WS_FLOATS + WIH_FLOATS + XS_FLOATS + BIAS_FLOATS + OUT_FLOATS)
#define SMEM_BYTES  (SMEM_FLOATS * 4)      // 222976 bytes

__global__ __launch_bounds__(NTHREADS, 1)
void lstm_kernel(const float* __restrict__ x,      // [B, 5, 13]
                 const float* __restrict__ b_ih,   // [1024]
                 const float* __restrict__ b_hh,   // [1024]
                 const float* __restrict__ W1,     // [6, 1280]
                 const float* __restrict__ b1,     // [6]
                 float* __restrict__ out) {        // [B, 6]
    extern __shared__ float smem[];
    float* Hs    = smem;                          // [2][256][64] k-major
    float* Ws    = Hs + HS_FLOATS;                // [16][256]
    float* WihS  = Ws + WS_FLOATS;                // [13][1024]
    float* Xs    = WihS + WIH_FLOATS;             // [5][13][64]
    float* biasS = Xs + XS_FLOATS;                // [1024]
    float* outS  = biasS + BIAS_FLOATS;           // [6][64]  (oc*64+row)

    const int tid = threadIdx.x;
    const int tx  = tid & 15;        // 16 column-groups
    const int ty  = tid >> 4;        // 16 row-groups (4 rows each)
    const int row0 = blockIdx.x * BM;

    // ---- stage per-block constants ----
    for (int i = tid; i < WIH_FLOATS; i += NTHREADS) WihS[i] = g_WihT[i];
    for (int i = tid; i < GATES; i += NTHREADS)      biasS[i] = b_ih[i] + b_hh[i];
    // input tile, transposed to [t][k][row]
    for (int i = tid; i < BM * SEQ * INPUT; i += NTHREADS) {
        int row = i / (SEQ * INPUT);
        int j   = i % (SEQ * INPUT);
        Xs[j * BM + row] = x[(size_t)(row0 + row) * (SEQ * INPUT) + j];
    }
    for (int i = tid; i < OUTD * BM; i += NTHREADS) outS[i] = b1[i >> 6];
    __syncthreads();

    // cell state: [chunk][r][j] -> 64 registers
    float c_reg[64];
    #pragma unroll
    for (int i = 0; i < 64; i++) c_reg[i] = 0.0f;

    for (int t = 0; t < SEQ; t++) {
        const int cur = t & 1, nxt = cur ^ 1;
        float* Hcur = Hs + cur * HIDDEN * BM;
        float* Hnxt = Hs + nxt * HIDDEN * BM;

        #pragma unroll
        for (int chunk = 0; chunk < 4; chunk++) {
            const int colb = chunk * 64 + tx * 4;   // h-col base for this thread
            float acc[64];                          // [r][g*4+j]

            // init with gate bias (same for all 4 rows)
            #pragma unroll
            for (int g = 0; g < 4; g++) {
                float4 bv = *(const float4*)&biasS[g * HIDDEN + colb];
                #pragma unroll
                for (int r = 0; r < 4; r++) {
                    acc[r * 16 + g * 4 + 0] = bv.x;
                    acc[r * 16 + g * 4 + 1] = bv.y;
                    acc[r * 16 + g * 4 + 2] = bv.z;
                    acc[r * 16 + g * 4 + 3] = bv.w;
                }
            }

            // input projection: K = 13
            #pragma unroll
            for (int k = 0; k < INPUT; k++) {
                float4 a = *(const float4*)&Xs[(t * INPUT + k) * BM + ty * 4];
                float av[4] = {a.x, a.y, a.z, a.w};
                #pragma unroll
                for (int g = 0; g < 4; g++) {
                    float4 b = *(const float4*)&WihS[k * GATES + g * HIDDEN + colb];
                    float bv[4] = {b.x, b.y, b.z, b.w};
                    #pragma unroll
                    for (int r = 0; r < 4; r++)
                        #pragma unroll
                        for (int j = 0; j < 4; j++)
                            acc[r * 16 + g * 4 + j] += av[r] * bv[j];
                }
            }

            // recurrent GEMM: K = 256 (skip at t=0 since h0 = 0)
            if (t > 0) {
                for (int k0 = 0; k0 < HIDDEN; k0 += 16) {
                    __syncthreads();   // protect Ws reuse
                    {
                        const int kk = tid >> 4, c = tid & 15;
                        const float* src = g_Wt + (size_t)(k0 + kk) * GATES;
                        #pragma unroll
                        for (int q = 0; q < 4; q++) {
                            int n  = c * 16 + q * 4;
                            int gr = (n >> 6) * HIDDEN + chunk * 64 + (n & 63);
                            *(float4*)&Ws[kk * 256 + n] = *(const float4*)&src[gr];
                        }
                    }
                    __syncthreads();
                    #pragma unroll 4
                    for (int kk = 0; kk < 16; kk++) {
                        float4 a = *(const float4*)&Hcur[(k0 + kk) * BM + ty * 4];
                        float av[4] = {a.x, a.y, a.z, a.w};
                        #pragma unroll
                        for (int g = 0; g < 4; g++) {
                            float4 b = *(const float4*)&Ws[kk * 256 + g * 64 + tx * 4];
                            float bv[4] = {b.x, b.y, b.z, b.w};
                            #pragma unroll
                            for (int r = 0; r < 4; r++)
                                #pragma unroll
                                for (int j = 0; j < 4; j++)
                                    acc[r * 16 + g * 4 + j] += av[r] * bv[j];
                        }
                    }
                }
            }

            // fused LSTM pointwise; write h to next buffer (k-major)
            #pragma unroll
            for (int j = 0; j < 4; j++) {
                float hv[4];
                #pragma unroll
                for (int r = 0; r < 4; r++) {
                    float ig = fast_sigmoid(acc[r * 16 + 0  + j]);
                    float fg = fast_sigmoid(acc[r * 16 + 4  + j]);
                    float gg = fast_tanh   (acc[r * 16 + 8  + j]);
                    float og = fast_sigmoid(acc[r * 16 + 12 + j]);
                    int ci = chunk * 16 + r * 4 + j;
                    float cn = fg * c_reg[ci] + ig * gg;
                    c_reg[ci] = cn;
                    hv[r] = og * fast_tanh(cn);
                }
                *(float4*)&Hnxt[(colb + j) * BM + ty * 4] =
                    make_float4(hv[0], hv[1], hv[2], hv[3]);
            }
        }
        __syncthreads();   // all h(t) written before projection reads

        // accumulate output projection for this timestep
        for (int task = tid; task < OUTD * BM; task += NTHREADS) {
            int row = task & 63, oc = task >> 6;
            const float* w = W1 + (size_t)oc * (SEQ * HIDDEN) + t * HIDDEN;
            float sum = 0.0f;
            #pragma unroll 8
            for (int k = 0; k < HIDDEN; k++)
                sum += Hnxt[k * BM + row] * w[k];
            outS[task] += sum;
        }
        __syncthreads();
    }

    for (int task = tid; task < OUTD * BM; task += NTHREADS) {
        int row = task & 63, oc = task >> 6;
        out[(size_t)(row0 + row) * OUTD + oc] = outS[task];
    }
}

extern "C" void kernel_launch(void* const* d_in, const int* in_sizes, int n_in,
                              void* d_out, int out_size) {
    const float* x    = (const float*)d_in[0];
    const float* W_ih = (const float*)d_in[1];
    const float* W_hh = (const float*)d_in[2];
    const float* b_ih = (const float*)d_in[3];
    const float* b_hh = (const float*)d_in[4];
    const float* W1   = (const float*)d_in[5];
    const float* b1   = (const float*)d_in[6];
    float* out = (float*)d_out;

    int B = in_sizes[0] / (SEQ * INPUT);

    prep_kernel<<<(HIDDEN * GATES + 255) / 256, 256>>>(W_ih, W_hh);

    cudaFuncSetAttribute(lstm_kernel,
                         cudaFuncAttributeMaxDynamicSharedMemorySize, SMEM_BYTES);
    lstm_kernel<<<B / BM, NTHREADS, SMEM_BYTES>>>(x, b_ih, b_hh, W1, b1, out);
}